// round 12
// baseline (speedup 1.0000x reference)
#include <cuda_runtime.h>
#include <cuda_bf16.h>
#include <mma.h>
#include <math.h>

using namespace nvcuda;

#define BB   8
#define NSEQ 512
#define DMODEL 512
#define HH   8
#define DHD  64
#define NPOS 121
#define EPSF 1e-7f

typedef unsigned long long ull;
typedef unsigned int u32;
typedef unsigned short u16;
typedef __nv_bfloat16 bf;

// ---------------- scratch ----------------
__device__ float g_q [BB*HH*NSEQ*DHD];
__device__ float g_k [BB*HH*NSEQ*DHD];
__device__ float g_v [BB*HH*NSEQ*DHD];
__device__ float g_qp[BB*HH*NSEQ*128];
__device__ float g_maps[(size_t)BB*HH*NSEQ*NSEQ];   // planar (b,h,n,m)
__device__ uint4 g_mh[(size_t)BB*NSEQ*NSEQ];        // NHWC8 maps hi
__device__ uint4 g_ml[(size_t)BB*NSEQ*NSEQ];        // NHWC8 maps lo
__device__ uint4 g_y1h[(size_t)BB*NSEQ*NSEQ*2];     // y1 NHWC16 hi (pix*2+half)
__device__ uint4 g_y1l[(size_t)BB*NSEQ*NSEQ*2];     // y1 NHWC16 lo
__device__ float g_part[(size_t)128*1024*2];
__device__ float g_nrm [128*2];
__device__ float g_ctx [BB*NSEQ*DMODEL];
__device__ float g_tmp [BB*NSEQ*DMODEL];

// ---------------- f32x2 helpers ----------------
__device__ __forceinline__ ull pk2(float a, float b){
    ull r; asm("mov.b64 %0, {%1,%2};" : "=l"(r) : "f"(a), "f"(b)); return r;
}
__device__ __forceinline__ void upk2(ull v, float& a, float& b){
    asm("mov.b64 {%0,%1}, %2;" : "=f"(a), "=f"(b) : "l"(v));
}
__device__ __forceinline__ void fma2(ull& d, ull a, ull b){
    asm("fma.rn.f32x2 %0, %1, %2, %3;" : "=l"(d) : "l"(a), "l"(b), "l"(d));
}

// ---------------- bf16 helpers ----------------
__device__ __forceinline__ u16 bfh(float x){ return __bfloat16_as_ushort(__float2bfloat16(x)); }
__device__ __forceinline__ float bf2f(u16 u){ return __bfloat162float(__ushort_as_bfloat16(u)); }
__device__ __forceinline__ uint4 pck8(const u16* s){
    uint4 u;
    u.x=(u32)s[0]|((u32)s[1]<<16); u.y=(u32)s[2]|((u32)s[3]<<16);
    u.z=(u32)s[4]|((u32)s[5]<<16); u.w=(u32)s[6]|((u32)s[7]<<16);
    return u;
}
__device__ __forceinline__ void unp8(uint4 u, float* v){
    v[0]=bf2f(u.x&0xffff); v[1]=bf2f(u.x>>16); v[2]=bf2f(u.y&0xffff); v[3]=bf2f(u.y>>16);
    v[4]=bf2f(u.z&0xffff); v[5]=bf2f(u.z>>16); v[6]=bf2f(u.w&0xffff); v[7]=bf2f(u.w>>16);
}

// ---------------- K1: QKV ----------------
__global__ void k_qkv(const float* __restrict__ A,
                      const float* __restrict__ Wq, const float* __restrict__ bq,
                      const float* __restrict__ Wk, const float* __restrict__ bk,
                      const float* __restrict__ Wv, const float* __restrict__ bv)
{
    __shared__ __align__(16) float As[16][68];
    __shared__ __align__(16) float Bs[16][68];
    int which = blockIdx.z;
    const float* W    = (which==0)?Wq:((which==1)?Wk:Wv);
    const float* bias = (which==0)?bq:((which==1)?bk:bv);
    float* C          = (which==0)?g_q:((which==1)?g_k:g_v);
    int m0 = blockIdx.y*64, n0 = blockIdx.x*64;
    int tx = threadIdx.x, ty = threadIdx.y;
    int tid = ty*16 + tx;
    int kk = tid & 15, mrow = tid >> 4;
    int nn = tid & 63, kb = tid >> 6;
    ull acc[4][2];
    #pragma unroll
    for (int i=0;i<4;i++){ acc[i][0]=0ull; acc[i][1]=0ull; }
    float pa[4], pb[4];
    #pragma unroll
    for (int i=0;i<4;i++) pa[i] = A[(size_t)(m0 + mrow + 16*i)*DMODEL + kk];
    #pragma unroll
    for (int j=0;j<4;j++) pb[j] = W[(size_t)(kb*4 + j)*DMODEL + n0 + nn];
    for (int k0 = 0; k0 < DMODEL; k0 += 16) {
        #pragma unroll
        for (int i=0;i<4;i++) As[kk][mrow + 16*i] = pa[i];
        #pragma unroll
        for (int j=0;j<4;j++) Bs[kb*4+j][nn] = pb[j];
        __syncthreads();
        if (k0 + 16 < DMODEL){
            #pragma unroll
            for (int i=0;i<4;i++) pa[i] = A[(size_t)(m0 + mrow + 16*i)*DMODEL + k0 + 16 + kk];
            #pragma unroll
            for (int j=0;j<4;j++) pb[j] = W[(size_t)(k0 + 16 + kb*4 + j)*DMODEL + n0 + nn];
        }
        #pragma unroll
        for (int k2=0; k2<16; k2++) {
            float4 a = *(const float4*)&As[k2][ty*4];
            ulonglong2 b = *(const ulonglong2*)&Bs[k2][tx*4];
            ull aa[4] = {pk2(a.x,a.x), pk2(a.y,a.y), pk2(a.z,a.z), pk2(a.w,a.w)};
            #pragma unroll
            for (int i=0;i<4;i++){ fma2(acc[i][0], aa[i], b.x); fma2(acc[i][1], aa[i], b.y); }
        }
        __syncthreads();
    }
    #pragma unroll
    for (int i=0;i<4;i++){
        int row = m0 + ty*4 + i;
        int bidx = row >> 9, nidx = row & 511;
        float v[4]; upk2(acc[i][0], v[0], v[1]); upk2(acc[i][1], v[2], v[3]);
        #pragma unroll
        for (int j=0;j<4;j++){
            int c = n0 + tx*4 + j;
            int h = c >> 6, dh = c & 63;
            C[(((size_t)(bidx*HH + h))*NSEQ + nidx)*DHD + dh] = v[j] + bias[c];
        }
    }
}

// ---------------- K2: qp ----------------
__global__ void k_qp(const float* __restrict__ posk)
{
    __shared__ __align__(16) float As[16][68];
    __shared__ __align__(16) float Bs[16][132];
    int m0 = blockIdx.x * 64;
    int tx = threadIdx.x, ty = threadIdx.y;
    int tid = ty*16 + tx;
    int kk = tid & 15, mrow = tid >> 4;
    int r = tid & 127, kh = tid >> 7;
    ull acc[4][4];
    #pragma unroll
    for (int i=0;i<4;i++){ acc[i][0]=0ull; acc[i][1]=0ull; acc[i][2]=0ull; acc[i][3]=0ull; }
    float pa[4], pb[8];
    #pragma unroll
    for (int i=0;i<4;i++) pa[i] = g_q[(size_t)(m0 + mrow + 16*i)*64 + kk];
    #pragma unroll
    for (int j=0;j<8;j++) pb[j] = (r < NPOS) ? posk[r*64 + kh*8 + j] : 0.f;
    for (int k0 = 0; k0 < 64; k0 += 16) {
        #pragma unroll
        for (int i=0;i<4;i++) As[kk][mrow + 16*i] = pa[i];
        #pragma unroll
        for (int j=0;j<8;j++) Bs[kh*8+j][r] = pb[j];
        __syncthreads();
        if (k0 + 16 < 64){
            #pragma unroll
            for (int i=0;i<4;i++) pa[i] = g_q[(size_t)(m0 + mrow + 16*i)*64 + k0 + 16 + kk];
            #pragma unroll
            for (int j=0;j<8;j++) pb[j] = (r < NPOS) ? posk[r*64 + k0 + 16 + kh*8 + j] : 0.f;
        }
        #pragma unroll
        for (int k2=0; k2<16; k2++){
            float4 a  = *(const float4*)&As[k2][ty*4];
            ulonglong2 b0 = *(const ulonglong2*)&Bs[k2][tx*8];
            ulonglong2 b1 = *(const ulonglong2*)&Bs[k2][tx*8+4];
            ull aa[4] = {pk2(a.x,a.x), pk2(a.y,a.y), pk2(a.z,a.z), pk2(a.w,a.w)};
            #pragma unroll
            for (int i=0;i<4;i++){
                fma2(acc[i][0], aa[i], b0.x); fma2(acc[i][1], aa[i], b0.y);
                fma2(acc[i][2], aa[i], b1.x); fma2(acc[i][3], aa[i], b1.y);
            }
        }
        __syncthreads();
    }
    #pragma unroll
    for (int i=0;i<4;i++){
        int row = m0 + ty*4 + i;
        float v[8];
        #pragma unroll
        for (int j=0;j<4;j++) upk2(acc[i][j], v[2*j], v[2*j+1]);
        #pragma unroll
        for (int j=0;j<8;j++){
            int c = tx*8 + j;
            if (c < NPOS) g_qp[(size_t)row*128 + c] = v[j];
        }
    }
}

// ---------------- K3: scores ----------------
__global__ void k_scores()
{
    __shared__ __align__(16) float As[16][68];
    __shared__ __align__(16) float Bs[16][68];
    int bh = blockIdx.z;
    const float* qb  = g_q  + (size_t)bh*NSEQ*DHD;
    const float* kb_ = g_k  + (size_t)bh*NSEQ*DHD;
    const float* qpb = g_qp + (size_t)bh*NSEQ*128;
    float* outb = g_maps + (size_t)bh*NSEQ*NSEQ;
    int n0 = blockIdx.y*64, m0 = blockIdx.x*64;
    int tx = threadIdx.x, ty = threadIdx.y;
    int tid = ty*16 + tx;
    int kk = tid & 15, rr = tid >> 4;
    ull acc[4][2];
    #pragma unroll
    for (int i=0;i<4;i++){ acc[i][0]=0ull; acc[i][1]=0ull; }
    float pa[4], pb[4];
    #pragma unroll
    for (int i=0;i<4;i++) pa[i] = qb [(size_t)(n0 + rr + 16*i)*DHD + kk];
    #pragma unroll
    for (int i=0;i<4;i++) pb[i] = kb_[(size_t)(m0 + rr + 16*i)*DHD + kk];
    for (int k0 = 0; k0 < DHD; k0 += 16) {
        #pragma unroll
        for (int i=0;i<4;i++) As[kk][rr + 16*i] = pa[i];
        #pragma unroll
        for (int i=0;i<4;i++) Bs[kk][rr + 16*i] = pb[i];
        __syncthreads();
        if (k0 + 16 < DHD){
            #pragma unroll
            for (int i=0;i<4;i++) pa[i] = qb [(size_t)(n0 + rr + 16*i)*DHD + k0 + 16 + kk];
            #pragma unroll
            for (int i=0;i<4;i++) pb[i] = kb_[(size_t)(m0 + rr + 16*i)*DHD + k0 + 16 + kk];
        }
        #pragma unroll
        for (int k2=0; k2<16; k2++){
            float4 a = *(const float4*)&As[k2][ty*4];
            ulonglong2 b = *(const ulonglong2*)&Bs[k2][tx*4];
            ull aa[4] = {pk2(a.x,a.x), pk2(a.y,a.y), pk2(a.z,a.z), pk2(a.w,a.w)};
            #pragma unroll
            for (int i=0;i<4;i++){ fma2(acc[i][0], aa[i], b.x); fma2(acc[i][1], aa[i], b.y); }
        }
        __syncthreads();
    }
    #pragma unroll
    for (int i=0;i<4;i++){
        int n = n0 + ty*4 + i;
        float v[4]; upk2(acc[i][0], v[0], v[1]); upk2(acc[i][1], v[2], v[3]);
        #pragma unroll
        for (int j=0;j<4;j++){
            int m = m0 + tx*4 + j;
            int rel = m - n;
            rel = min(60, max(-60, rel)) + 60;
            outb[(size_t)n*NSEQ + m] = (v[j] + qpb[(size_t)n*128 + rel]) * 0.125f;
        }
    }
}

// ---------------- NHWC8 split transpose (planar fp32 -> hi/lo bf16) ----------------
__global__ void k_nhwc()
{
    __shared__ float s[8][264];
    int m0 = blockIdx.x*256, n = blockIdx.y, b = blockIdx.z;
    int t = threadIdx.x;
    int h = t >> 5, l = t & 31;
    #pragma unroll
    for (int j=0;j<8;j++){
        int m = l + 32*j;
        s[h][m] = g_maps[((size_t)(b*8+h)*NSEQ + n)*NSEQ + m0 + m];
    }
    __syncthreads();
    float v[8];
    #pragma unroll
    for (int c=0;c<8;c++) v[c] = s[c][t];
    u16 hi[8], lo[8];
    #pragma unroll
    for (int c=0;c<8;c++){ hi[c]=bfh(v[c]); lo[c]=bfh(v[c]-bf2f(hi[c])); }
    size_t pix = ((size_t)(b*NSEQ + n))*NSEQ + m0 + t;
    g_mh[pix] = pck8(hi);
    g_ml[pix] = pck8(lo);
}

// ---------------- conv1 WMMA: NHWC8 maps -> y1 NHWC16, fused stats ----------------
// grid (8, 128, 8), 256 threads. Tile: 4 rows x 64 px, 16 oc.
#define C1_PW 72
#define C1_PSZ (8*C1_PW*16)      // 9216 elements per split
#define C1_BSZ (15*256)          // 3840 elements per split
__global__ void k_conv1w(const float* __restrict__ w, const float* __restrict__ bias,
                         const int* __restrict__ valid_len)
{
    extern __shared__ __align__(128) char smraw[];
    bf* pH = (bf*)smraw;
    bf* pL = pH + C1_PSZ;
    bf* bHs = pL + C1_PSZ;
    bf* bLs = bHs + C1_BSZ;
    int tid = threadIdx.x;
    int x0 = blockIdx.x*64, y0 = blockIdx.y*4, b = blockIdx.z;
    int vlen = valid_len[b];

    // fill paired patch: px slot holds [ch0-7 of px | ch0-7 of px+1]
    for (int idx = tid; idx < 8*C1_PW; idx += 256){
        int rr = idx / C1_PW, cc = idx - rr*C1_PW;
        int gy = y0-2+rr, gx = x0-2+cc;
        uint4 h = make_uint4(0,0,0,0), l = make_uint4(0,0,0,0);
        if ((unsigned)gy < NSEQ && (unsigned)gx < NSEQ){
            size_t pix = ((size_t)(b*NSEQ+gy))*NSEQ + gx;
            h = g_mh[pix]; l = g_ml[pix];
        }
        int e = idx*16;
        *(uint4*)(pH + e) = h;
        *(uint4*)(pL + e) = l;
        if (cc){
            *(uint4*)(pH + e - 8) = h;   // high half of previous pixel
            *(uint4*)(pL + e - 8) = l;
        }
    }
    // build B: pair p=(dy*3+dxp), k = (dxoff<<3)|ic, n = oc
    for (int idx = tid; idx < 15*256; idx += 256){
        int n = idx & 15, k = (idx>>4) & 15, p = idx >> 8;
        int dy = p/3, dxp = p%3;
        int dx = dxp*2 + (k>>3);
        float v = (dx < 5) ? w[((dy*5+dx)*8 + (k&7))*16 + n] : 0.f;
        u16 hh = bfh(v);
        bHs[idx] = __ushort_as_bfloat16(hh);
        bLs[idx] = __float2bfloat16(v - bf2f(hh));
    }
    __syncthreads();

    int w8 = tid >> 5, lane = tid & 31;
    int r = w8 >> 2, t = w8 & 3;           // tile0=(r,t), tile1=(r+2,t)
    wmma::fragment<wmma::accumulator,16,16,16,float> acc0, acc1;
    wmma::fill_fragment(acc0, 0.f);
    wmma::fill_fragment(acc1, 0.f);
    #pragma unroll
    for (int p=0; p<15; p++){
        int dy = p/3, dxp = p - 3*(p/3);
        const bf* a0 = pH + ((r+dy)*C1_PW + t*16 + dxp*2)*16;
        const bf* a1 = pH + ((r+2+dy)*C1_PW + t*16 + dxp*2)*16;
        const bf* a0l = a0 + C1_PSZ;       // pL is contiguous after pH
        const bf* a1l = a1 + C1_PSZ;
        wmma::fragment<wmma::matrix_a,16,16,16,bf,wmma::row_major> aH0, aL0, aH1, aL1;
        wmma::fragment<wmma::matrix_b,16,16,16,bf,wmma::row_major> bHf, bLf;
        wmma::load_matrix_sync(aH0, a0, 16);
        wmma::load_matrix_sync(aH1, a1, 16);
        wmma::load_matrix_sync(aL0, a0l, 16);
        wmma::load_matrix_sync(aL1, a1l, 16);
        wmma::load_matrix_sync(bHf, bHs + p*256, 16);
        wmma::load_matrix_sync(bLf, bLs + p*256, 16);
        wmma::mma_sync(acc0, aH0, bHf, acc0);
        wmma::mma_sync(acc1, aH1, bHf, acc1);
        wmma::mma_sync(acc0, aH0, bLf, acc0);
        wmma::mma_sync(acc1, aH1, bLf, acc1);
        wmma::mma_sync(acc0, aL0, bHf, acc0);
        wmma::mma_sync(acc1, aL1, bHf, acc1);
    }
    __syncthreads();      // patch no longer needed; reuse smem

    float* wb = (float*)smraw + w8*256;
    float* statb = (float*)smraw + 2048;
    int px = lane >> 1, half = lane & 1;
    float sums[8] = {0,0,0,0,0,0,0,0}, sqs[8] = {0,0,0,0,0,0,0,0};
    #pragma unroll
    for (int tile=0; tile<2; tile++){
        wmma::store_matrix_sync(wb, tile ? acc1 : acc0, 16, wmma::mem_row_major);
        __syncwarp();
        int y = y0 + r + tile*2;
        float v[8];
        #pragma unroll
        for (int j=0;j<8;j++) v[j] = wb[px*16 + half*8 + j] + bias[half*8+j];
        u16 hh[8], ll[8];
        #pragma unroll
        for (int j=0;j<8;j++){ hh[j] = bfh(v[j]); ll[j] = bfh(v[j] - bf2f(hh[j])); }
        size_t pix = ((size_t)(b*NSEQ+y))*NSEQ + x0 + t*16 + px;
        g_y1h[pix*2 + half] = pck8(hh);
        g_y1l[pix*2 + half] = pck8(ll);
        if (y < vlen){
            #pragma unroll
            for (int j=0;j<8;j++){ sums[j] += v[j]; sqs[j] += v[j]*v[j]; }
        }
        __syncwarp();
    }
    // reduce over px lanes (same parity): offsets 2,4,8,16
    #pragma unroll
    for (int j=0;j<8;j++){
        #pragma unroll
        for (int o=2;o<=16;o<<=1){
            sums[j] += __shfl_xor_sync(0xffffffffu, sums[j], o);
            sqs[j]  += __shfl_xor_sync(0xffffffffu, sqs[j],  o);
        }
    }
    if (lane < 2){
        #pragma unroll
        for (int j=0;j<8;j++){
            statb[(w8*2+lane)*16 + j*2    ] = sums[j];
            statb[(w8*2+lane)*16 + j*2 + 1] = sqs[j];
        }
    }
    __syncthreads();
    if (tid < 32){
        int ch = tid >> 1, sq = tid & 1;
        float rsum = 0.f;
        #pragma unroll
        for (int wi=0; wi<8; wi++)
            rsum += statb[(wi*2 + (ch>>3))*16 + (ch&7)*2 + sq];
        int tile = blockIdx.y*8 + blockIdx.x;
        g_part[(((size_t)(b*16+ch))*1024 + tile)*2 + sq] = rsum;
    }
}

// ---------------- norm finalize: grid 128 blocks ----------------
__global__ void k_nrm(const int* __restrict__ valid_len,
                      const float* __restrict__ gamma, const float* __restrict__ beta)
{
    __shared__ float ss[256], qq[256];
    int bc = blockIdx.x;
    float s = 0.f, q = 0.f;
    for (int i = threadIdx.x; i < 1024; i += 256){
        s += g_part[((size_t)bc*1024 + i)*2];
        q += g_part[((size_t)bc*1024 + i)*2 + 1];
    }
    ss[threadIdx.x] = s; qq[threadIdx.x] = q;
    __syncthreads();
    for (int o = 128; o; o >>= 1){
        if (threadIdx.x < o){ ss[threadIdx.x] += ss[threadIdx.x+o]; qq[threadIdx.x] += qq[threadIdx.x+o]; }
        __syncthreads();
    }
    if (threadIdx.x == 0){
        int b = bc >> 4, c = bc & 15;
        float cnt = (float)valid_len[b] * (float)NSEQ;
        float mean = ss[0] / cnt;
        float var = fmaxf(qq[0] / cnt - mean*mean, 0.f);
        float scale = gamma[c] * rsqrtf(var + EPSF);
        g_nrm[bc*2]     = scale;
        g_nrm[bc*2 + 1] = beta[c] - mean*scale;
    }
}

// ---------------- conv2 WMMA: y1 NHWC16 (norm+relu in fill) -> maps planar ----------------
// grid (8, 128, 8), 256 threads. Tile: 4 rows x 64 px, 8 oc. m32n8k16.
#define C2_PW 68
#define C2_PSZ (8*C2_PW*16)      // 8704 elements per split
#define C2_BSZ (25*128)          // 3200 elements per split
__global__ void k_conv2w(const float* __restrict__ w, const float* __restrict__ bias)
{
    extern __shared__ __align__(128) char smraw[];
    bf* pH = (bf*)smraw;
    bf* pL = pH + C2_PSZ;
    bf* bHs = pL + C2_PSZ;
    bf* bLs = bHs + C2_BSZ;
    __shared__ float sc[16], sh[16];
    int tid = threadIdx.x;
    int x0 = blockIdx.x*64, y0 = blockIdx.y*4, b = blockIdx.z;

    if (tid < 16){
        sc[tid] = g_nrm[(b*16+tid)*2];
        sh[tid] = g_nrm[(b*16+tid)*2+1];
    }
    // build B: tap t_=(dy*5+dx), k = ic(16), n = oc(8)
    for (int idx = tid; idx < 25*128; idx += 256){
        int n = idx & 7, k = (idx>>3) & 15, t_ = idx >> 7;
        float v = w[(t_*16 + k)*8 + n];
        u16 hh = bfh(v);
        bHs[idx] = __ushort_as_bfloat16(hh);
        bLs[idx] = __float2bfloat16(v - bf2f(hh));
    }
    __syncthreads();     // sc/sh visible
    // fill patch: NHWC16 with norm+relu+resplit
    for (int idx = tid; idx < 8*C2_PW; idx += 256){
        int rr = idx / C2_PW, cc = idx - rr*C2_PW;
        int gy = y0-2+rr, gx = x0-2+cc;
        float v[16];
        if ((unsigned)gy < NSEQ && (unsigned)gx < NSEQ){
            size_t pix = ((size_t)(b*NSEQ+gy))*NSEQ + gx;
            float vh[16], vl[16];
            unp8(g_y1h[pix*2],   vh);   unp8(g_y1h[pix*2+1], vh+8);
            unp8(g_y1l[pix*2],   vl);   unp8(g_y1l[pix*2+1], vl+8);
            #pragma unroll
            for (int c=0;c<16;c++) v[c] = fmaxf(fmaf(vh[c]+vl[c], sc[c], sh[c]), 0.f);
        } else {
            #pragma unroll
            for (int c=0;c<16;c++) v[c] = 0.f;
        }
        u16 hh[16], ll[16];
        #pragma unroll
        for (int c=0;c<16;c++){ hh[c] = bfh(v[c]); ll[c] = bfh(v[c] - bf2f(hh[c])); }
        int e = idx*16;
        *(uint4*)(pH + e)     = pck8(hh);
        *(uint4*)(pH + e + 8) = pck8(hh+8);
        *(uint4*)(pL + e)     = pck8(ll);
        *(uint4*)(pL + e + 8) = pck8(ll+8);
    }
    __syncthreads();

    int w8 = tid >> 5, lane = tid & 31;
    int r = w8 >> 1, t = w8 & 1;          // 4 rows x 2 xtiles(32px)
    wmma::fragment<wmma::accumulator,32,8,16,float> acc;
    wmma::fill_fragment(acc, 0.f);
    #pragma unroll
    for (int tap=0; tap<25; tap++){
        int dy = tap/5, dx = tap - 5*(tap/5);
        const bf* a = pH + ((r+dy)*C2_PW + t*32 + dx)*16;
        const bf* al = a + C2_PSZ;
        wmma::fragment<wmma::matrix_a,32,8,16,bf,wmma::row_major> aH, aL;
        wmma::fragment<wmma::matrix_b,32,8,16,bf,wmma::row_major> bHf, bLf;
        wmma::load_matrix_sync(aH, a, 16);
        wmma::load_matrix_sync(aL, al, 16);
        wmma::load_matrix_sync(bHf, bHs + tap*128, 8);
        wmma::load_matrix_sync(bLf, bLs + tap*128, 8);
        wmma::mma_sync(acc, aH, bHf, acc);
        wmma::mma_sync(acc, aH, bLf, acc);
        wmma::mma_sync(acc, aL, bHf, acc);
    }
    __syncthreads();      // patch no longer needed
    float* wb = (float*)smraw + w8*256;
    wmma::store_matrix_sync(wb, acc, 8, wmma::mem_row_major);
    __syncwarp();
    int y = y0 + r;
    int x = x0 + t*32 + lane;
    #pragma unroll
    for (int oc=0; oc<8; oc++)
        g_maps[(((size_t)(b*8+oc))*NSEQ + y)*NSEQ + x] = wb[lane*8 + oc] + bias[oc];
}

// ---------------- masked softmax ----------------
__global__ void k_softmax(const int* __restrict__ valid_len)
{
    int warp = threadIdx.x >> 5, lane = threadIdx.x & 31;
    int row = blockIdx.x*8 + warp;
    int b = row >> 12;
    int valid = valid_len[b];
    float* p = g_maps + (size_t)row*NSEQ;
    float v[16]; float mx = -1e30f;
    #pragma unroll
    for (int j=0;j<16;j++){
        int m = lane + 32*j;
        float x = (m < valid) ? p[m] : -1e30f;
        v[j] = x; mx = fmaxf(mx, x);
    }
    #pragma unroll
    for (int o=16;o;o>>=1) mx = fmaxf(mx, __shfl_xor_sync(0xffffffffu, mx, o));
    float s = 0.f;
    #pragma unroll
    for (int j=0;j<16;j++){
        int m = lane + 32*j;
        float e = (m < valid) ? __expf(v[j]-mx) : 0.f;
        v[j] = e; s += e;
    }
    #pragma unroll
    for (int o=16;o;o>>=1) s += __shfl_xor_sync(0xffffffffu, s, o);
    float inv = 1.f / s;
    #pragma unroll
    for (int j=0;j<16;j++) p[lane + 32*j] = v[j]*inv;
}

// ---------------- attn @ V -> ctx ----------------
__global__ void k_av()
{
    __shared__ __align__(16) float As[16][68];
    __shared__ __align__(16) float Bs[16][68];
    int bh = blockIdx.z;
    const float* ab = g_maps + (size_t)bh*NSEQ*NSEQ;
    const float* vb = g_v    + (size_t)bh*NSEQ*DHD;
    int n0 = blockIdx.y*64;
    int tx = threadIdx.x, ty = threadIdx.y;
    int tid = ty*16 + tx;
    int kk = tid & 15, rr = tid >> 4;
    int dd = tid & 63, kb4 = tid >> 6;
    ull acc[4][2];
    #pragma unroll
    for (int i=0;i<4;i++){ acc[i][0]=0ull; acc[i][1]=0ull; }
    float pa[4], pb[4];
    #pragma unroll
    for (int i=0;i<4;i++) pa[i] = ab[(size_t)(n0 + rr + 16*i)*NSEQ + kk];
    #pragma unroll
    for (int j=0;j<4;j++) pb[j] = vb[(size_t)(kb4*4 + j)*DHD + dd];
    for (int k0 = 0; k0 < NSEQ; k0 += 16){
        #pragma unroll
        for (int i=0;i<4;i++) As[kk][rr + 16*i] = pa[i];
        #pragma unroll
        for (int j=0;j<4;j++) Bs[kb4*4+j][dd] = pb[j];
        __syncthreads();
        if (k0 + 16 < NSEQ){
            #pragma unroll
            for (int i=0;i<4;i++) pa[i] = ab[(size_t)(n0 + rr + 16*i)*NSEQ + k0 + 16 + kk];
            #pragma unroll
            for (int j=0;j<4;j++) pb[j] = vb[(size_t)(k0 + 16 + kb4*4 + j)*DHD + dd];
        }
        #pragma unroll
        for (int k2=0; k2<16; k2++){
            float4 a = *(const float4*)&As[k2][ty*4];
            ulonglong2 b = *(const ulonglong2*)&Bs[k2][tx*4];
            ull aa[4] = {pk2(a.x,a.x), pk2(a.y,a.y), pk2(a.z,a.z), pk2(a.w,a.w)};
            #pragma unroll
            for (int i=0;i<4;i++){ fma2(acc[i][0], aa[i], b.x); fma2(acc[i][1], aa[i], b.y); }
        }
        __syncthreads();
    }
    int b = bh >> 3, h = bh & 7;
    #pragma unroll
    for (int i=0;i<4;i++){
        int n = n0 + ty*4 + i;
        float v[4]; upk2(acc[i][0], v[0], v[1]); upk2(acc[i][1], v[2], v[3]);
        #pragma unroll
        for (int j=0;j<4;j++){
            int d = h*64 + tx*4 + j;
            g_ctx[((size_t)(b*NSEQ + n))*DMODEL + d] = v[j];
        }
    }
}

// ---------------- out = ctx @ Wh + bh + query ----------------
__global__ void k_out(const float* __restrict__ Wh, const float* __restrict__ bhv,
                      const float* __restrict__ query)
{
    __shared__ __align__(16) float As[16][68];
    __shared__ __align__(16) float Bs[16][68];
    int m0 = blockIdx.y*64, n0 = blockIdx.x*64;
    int tx = threadIdx.x, ty = threadIdx.y;
    int tid = ty*16 + tx;
    int kk = tid & 15, mrow = tid >> 4;
    int nn = tid & 63, kb = tid >> 6;
    ull acc[4][2];
    #pragma unroll
    for (int i=0;i<4;i++){ acc[i][0]=0ull; acc[i][1]=0ull; }
    float pa[4], pb[4];
    #pragma unroll
    for (int i=0;i<4;i++) pa[i] = g_ctx[(size_t)(m0 + mrow + 16*i)*DMODEL + kk];
    #pragma unroll
    for (int j=0;j<4;j++) pb[j] = Wh[(size_t)(kb*4 + j)*DMODEL + n0 + nn];
    for (int k0 = 0; k0 < DMODEL; k0 += 16){
        #pragma unroll
        for (int i=0;i<4;i++) As[kk][mrow + 16*i] = pa[i];
        #pragma unroll
        for (int j=0;j<4;j++) Bs[kb*4+j][nn] = pb[j];
        __syncthreads();
        if (k0 + 16 < DMODEL){
            #pragma unroll
            for (int i=0;i<4;i++) pa[i] = g_ctx[(size_t)(m0 + mrow + 16*i)*DMODEL + k0 + 16 + kk];
            #pragma unroll
            for (int j=0;j<4;j++) pb[j] = Wh[(size_t)(k0 + 16 + kb*4 + j)*DMODEL + n0 + nn];
        }
        #pragma unroll
        for (int k2=0; k2<16; k2++){
            float4 a = *(const float4*)&As[k2][ty*4];
            ulonglong2 b = *(const ulonglong2*)&Bs[k2][tx*4];
            ull aa[4] = {pk2(a.x,a.x), pk2(a.y,a.y), pk2(a.z,a.z), pk2(a.w,a.w)};
            #pragma unroll
            for (int i=0;i<4;i++){ fma2(acc[i][0], aa[i], b.x); fma2(acc[i][1], aa[i], b.y); }
        }
        __syncthreads();
    }
    #pragma unroll
    for (int i=0;i<4;i++){
        int row = m0 + ty*4 + i;
        float v[4]; upk2(acc[i][0], v[0], v[1]); upk2(acc[i][1], v[2], v[3]);
        #pragma unroll
        for (int j=0;j<4;j++){
            int c = n0 + tx*4 + j;
            g_tmp[(size_t)row*DMODEL + c] = v[j] + bhv[c] + query[(size_t)row*DMODEL + c];
        }
    }
}

// ---------------- final layernorm ----------------
__global__ void k_ln(const float* __restrict__ gamma, const float* __restrict__ beta,
                     float* __restrict__ out)
{
    int warp = threadIdx.x >> 5, lane = threadIdx.x & 31;
    int row = blockIdx.x*8 + warp;
    const float* p = g_tmp + (size_t)row*DMODEL;
    float v[16]; float s = 0.f;
    #pragma unroll
    for (int j=0;j<16;j++){ v[j] = p[lane + 32*j]; s += v[j]; }
    #pragma unroll
    for (int o=16;o;o>>=1) s += __shfl_xor_sync(0xffffffffu, s, o);
    float mean = s * (1.f/512.f);
    float q = 0.f;
    #pragma unroll
    for (int j=0;j<16;j++){ float d = v[j]-mean; q += d*d; }
    #pragma unroll
    for (int o=16;o;o>>=1) q += __shfl_xor_sync(0xffffffffu, q, o);
    float rstd = rsqrtf(q * (1.f/512.f) + EPSF);
    #pragma unroll
    for (int j=0;j<16;j++){
        int c = lane + 32*j;
        out[(size_t)row*DMODEL + c] = gamma[c]*(v[j]-mean)*rstd + beta[c];
    }
}

// ---------------- launch ----------------
extern "C" void kernel_launch(void* const* d_in, const int* in_sizes, int n_in,
                              void* d_out, int out_size)
{
    const float* query   = (const float*)d_in[0];
    const int*   valid   = (const int*)  d_in[1];
    const float* Wq      = (const float*)d_in[2];
    const float* bq      = (const float*)d_in[3];
    const float* Wk      = (const float*)d_in[4];
    const float* bk      = (const float*)d_in[5];
    const float* Wv      = (const float*)d_in[6];
    const float* bv      = (const float*)d_in[7];
    const float* Wh      = (const float*)d_in[8];
    const float* bhv     = (const float*)d_in[9];
    const float* pos_k   = (const float*)d_in[10];
    const float* conv1_w = (const float*)d_in[11];
    const float* conv1_b = (const float*)d_in[12];
    const float* n1g     = (const float*)d_in[13];
    const float* n1b     = (const float*)d_in[14];
    const float* conv2_w = (const float*)d_in[15];
    const float* conv2_b = (const float*)d_in[16];
    const float* lng     = (const float*)d_in[17];
    const float* lnb     = (const float*)d_in[18];
    float* outp = (float*)d_out;

    int smem1 = (2*C1_PSZ + 2*C1_BSZ) * 2;   // 52224 bytes
    int smem2 = (2*C2_PSZ + 2*C2_BSZ) * 2;   // 47616 bytes
    static int inited = 0;
    if (!inited){
        cudaFuncSetAttribute(k_conv1w, cudaFuncAttributeMaxDynamicSharedMemorySize, smem1);
        cudaFuncSetAttribute(k_conv2w, cudaFuncAttributeMaxDynamicSharedMemorySize, smem2);
        inited = 1;
    }

    dim3 t16(16,16);
    k_qkv   <<<dim3(8,64,3),  t16>>>(query, Wq,bq, Wk,bk, Wv,bv);
    k_qp    <<<dim3(512,1,1), t16>>>(pos_k);
    k_scores<<<dim3(8,8,64),  t16>>>();
    k_nhwc  <<<dim3(2,512,8), 256>>>();
    k_conv1w<<<dim3(8,128,8), 256, smem1>>>(conv1_w, conv1_b, valid);
    k_nrm   <<<128, 256>>>(valid, n1g, n1b);
    k_conv2w<<<dim3(8,128,8), 256, smem2>>>(conv2_w, conv2_b);
    k_softmax<<<4096, 256>>>(valid);
    k_av    <<<dim3(1,8,64),  t16>>>();
    k_out   <<<dim3(8,64),    t16>>>(Wh, bhv, query);
    k_ln    <<<512, 256>>>(lng, lnb, outp);
}